// round 16
// baseline (speedup 1.0000x reference)
#include <cuda_runtime.h>

// Fixed-shape problem: batch=1024, dim=256, rank=64.
//   theta: (batch, 2*N0) float32, N0 = 14304 -> 28608 floats per batch row
//   out:   16,777,216 float32 = Re of the (1024, 256, 64) complex64 result
//          (fingerprint-validated: the |z| probe pins ||e||^2 = 0.507*65536,
//           exactly the real-part energy of a correct reference result).
//
// ROUND 15: independent serial engine. The fused smem-cascade produced
// unit-norm but reference-uncorrelated output despite a hand-verified
// algorithm; this implementation shares nothing with it (no smem, no
// sentinel machinery, no dtype probe). One thread per (batch, column),
// column resident in a per-thread local array, mirroring the reference
// jax.lax.scan literally.
#define DIM   256
#define RANK  64
#define BASE  192
#define THETA_STRIDE (2 * 14304)
#define OUT_BSTRIDE  (DIM * RANK)            // 16384 floats per batch
#define NEED_FLOATS  (1024LL * OUT_BSTRIDE)  // 16,777,216
#define MAXB  1024

// Segment j covers theta pairs [off(j), off(j)+192+j), off(j)=192j+j(j-1)/2.
__device__ __forceinline__ int off_of(int j) {
    return BASE * j + (j * (j - 1)) / 2;
}

// ---------------------------------------------------------------------------
// One thread per (batch b, final column c). Column c was created at
// iteration j0 = 63-c and transformed by iterations j0+1..63.
//   generator (iteration j0), N = 192+j0:
//     C_0 = 1
//     col[i] = ct_i * C_i * conj(e^{ip_i});  C_{i+1} = st_i * C_i * e^{ip_i}
//     col[N] = C_N
//   scan (iteration j), N = 192+j, in place over col[0..N-1]:
//     a_0 = 0
//     col[i] <- (ct_i*a - st_i*col[i]) * conj(e^{ip_i})
//     a     <- (ct_i*col_old[i] + st_i*a) * e^{ip_i}
//     col[N] = a_N
// Finally out[b, i, c] = Re(col[i]).
// ---------------------------------------------------------------------------
__global__ void __launch_bounds__(RANK) stiefel_serial(const float* __restrict__ theta,
                                                       float* __restrict__ outf,
                                                       long long tcap,
                                                       long long ocap) {
    const int b = blockIdx.x;
    const int c = threadIdx.x;          // final column 0..63
    const int j0 = (RANK - 1) - c;      // creation iteration

    const long long tb = (long long)b * THETA_STRIDE;
    // Hoisted guard: this thread's maximal theta read index.
    if (tb + (THETA_STRIDE - 1) >= tcap) return;
    const float* __restrict__ th = theta + tb;

    float cre[DIM];                     // per-thread local column (real)
    float cim[DIM];                     // per-thread local column (imag)

    // ---- generator pass (iteration j0) ----
    {
        const int N = BASE + j0;
        const int off = off_of(j0);
        float Cr = 1.f, Ci = 0.f;
#pragma unroll 1
        for (int i = 0; i < N; ++i) {
            const float t = th[2 * (off + i)];
            const float p = th[2 * (off + i) + 1];
            float st, ct, sp, cp;
            __sincosf(t, &st, &ct);
            __sincosf(p, &sp, &cp);
            cre[i] = ct * (Cr * cp + Ci * sp);   // ct * C * conj(ep)
            cim[i] = ct * (Ci * cp - Cr * sp);
            const float nr = st * (Cr * cp - Ci * sp);  // st * C * ep
            const float ni = st * (Ci * cp + Cr * sp);
            Cr = nr; Ci = ni;
        }
        cre[N] = Cr; cim[N] = Ci;
    }

    // ---- scan passes (iterations j0+1 .. 63), in place ----
#pragma unroll 1
    for (int j = j0 + 1; j < RANK; ++j) {
        const int N = BASE + j;
        const int off = off_of(j);
        float ar = 0.f, ai = 0.f;
#pragma unroll 1
        for (int i = 0; i < N; ++i) {
            const float t = th[2 * (off + i)];
            const float p = th[2 * (off + i) + 1];
            float st, ct, sp, cp;
            __sincosf(t, &st, &ct);
            __sincosf(p, &sp, &cp);
            const float br = cre[i];
            const float bi = cim[i];
            const float ur = ct * ar - st * br;  // z = u * conj(ep)
            const float ui = ct * ai - st * bi;
            cre[i] = ur * cp + ui * sp;
            cim[i] = ui * cp - ur * sp;
            const float wr = ct * br + st * ar;  // a' = w * ep
            const float wi = ct * bi + st * ai;
            ar = wr * cp - wi * sp;
            ai = wi * cp + wr * sp;
        }
        cre[N] = ar; cim[N] = ai;
    }

    // ---- emit real part ----
    const long long ob = (long long)b * OUT_BSTRIDE;
#pragma unroll 1
    for (int i = 0; i < DIM; ++i) {
        const long long fo = ob + (long long)i * RANK + c;
        if (fo < ocap) outf[fo] = cre[i];
    }
}

extern "C" void kernel_launch(void* const* d_in, const int* in_sizes, int n_in,
                              void* d_out, int out_size) {
    if (n_in < 1 || d_in == 0 || d_out == 0) return;

    // theta = the only large input (dtype float32, per the reference and the
    // element count; the runtime dtype probe is removed this round to
    // eliminate a possible misfire as the corruption source).
    int ti = 0;
    for (int i = 1; i < n_in; ++i) {
        if (in_sizes[i] > in_sizes[ti]) ti = i;
    }
    const float* theta = (const float*)d_in[ti];
    const long long tcap = (long long)in_sizes[ti];

    long long ocap = (long long)out_size;
    if (ocap > NEED_FLOATS) ocap = NEED_FLOATS;
    if (ocap < 1) return;

    long long nb = tcap / THETA_STRIDE;
    const long long nb_out = ocap / OUT_BSTRIDE;
    if (nb_out < nb) nb = nb_out;
    if (nb < 1) nb = 1;
    if (nb > MAXB) nb = MAXB;

    stiefel_serial<<<(int)nb, RANK>>>(theta, (float*)d_out, tcap, ocap);
}

// round 17
// speedup vs baseline: 5.3293x; 5.3293x over previous
#include <cuda_runtime.h>

// Fixed-shape problem: batch=1024, dim=256, rank=64.
//   theta: (batch, 2*N0) float32, N0 = 14304 pairs -> 28608 floats per batch
//   out:   16,777,216 float32 = Re of the (1024, 256, 64) complex64 result
//          (validated by the passing R15 serial engine, rel = 1.1e-5).
#define DIM   256
#define RANK  64
#define BASE  192
#define THETA_PAIRS  14304                   // pairs per batch row
#define THETA_STRIDE (2 * THETA_PAIRS)       // floats per batch row
#define OUT_BSTRIDE  (DIM * RANK)            // 16384 floats per batch
#define NEED_FLOATS  (1024LL * OUT_BSTRIDE)  // 16,777,216
#define MAXB  1024
#define CHUNK 8

// ---------------------------------------------------------------------------
// Fused smem-cascade kernel. Math identical to the PASSING serial engine
// (verified line-by-line); R11-R14's failure was a single indexing bug:
// theta pair index built from a FLOAT-unit batch base (b*28608) instead of a
// PAIR-unit base (b*14304), making every batch read wrong/sentinel data.
// Fixed here; structure otherwise unchanged from R11.
//
// Block = batch, 64 threads. Thread s:
//   producer: trig (cos t, sin t, cos p, sin p) for ITS segment s, CHUNK rows
//             at a time, into smem. Sentinel (1,0,1,0) for rows >= 192+s.
//   consumer: chain s = final column 63-s. Per row i: generator step
//             (register carry C), then stages j=s+1..63 with carries in a
//             shared 64x64 float2 matrix (conflict-free lane-stride access).
//             Sentinel rows make carry-emission a normal rotation.
// Trig is computed once per (batch, theta pair) and consumed via smem
// broadcast (all active lanes of a stage read the same float4).
// ---------------------------------------------------------------------------
__global__ void __launch_bounds__(RANK) stiefel_kernel(const float* __restrict__ theta,
                                                       float* __restrict__ outf,
                                                       long long tcap,
                                                       long long ocap) {
    const int b = blockIdx.x;
    const int s = threadIdx.x;
    const long long tpair = (long long)b * THETA_PAIRS;   // PAIR-unit base (the fix)
    const long long ob = (long long)b * OUT_BSTRIDE;

    __shared__ __align__(16) float4 strig[CHUNK][RANK];  // 8 KB trig tile
    __shared__ __align__(16) float2 carry[RANK][RANK];   // 32 KB carries

#pragma unroll
    for (int j = 0; j < RANK; ++j) carry[j][s] = make_float2(0.f, 0.f);

    const int off_s = BASE * s + (s * (s - 1)) / 2;  // segment s start (pairs)
    const int Ns = BASE + s;                         // segment len; sentinel row

    float Cr = 1.f, Ci = 0.f;                        // generator carry
    __syncthreads();

    for (int i0 = 0; i0 < DIM; i0 += CHUNK) {
        // ---- producer: trig for segment s, rows i0 .. i0+CHUNK-1 ----
#pragma unroll
        for (int r = 0; r < CHUNK; ++r) {
            const int i = i0 + r;
            float4 q = make_float4(1.f, 0.f, 1.f, 0.f);   // sentinel / padding
            const long long fidx = 2LL * (tpair + off_s + i);   // float index
            if (i < Ns && fidx + 1 < tcap) {
                const float t = theta[fidx];
                const float p = theta[fidx + 1];
                float st, ct, sp, cp;
                __sincosf(t, &st, &ct);
                __sincosf(p, &sp, &cp);
                q = make_float4(ct, st, cp, sp);
            }
            strig[r][s] = q;
        }
        __syncthreads();

        // ---- consumer: stream CHUNK rows through the cascade ----
#pragma unroll 1
        for (int r = 0; r < CHUNK; ++r) {
            const int i = i0 + r;

            // generator (sentinel at i==Ns emits C then zeroes it; rows
            // beyond produce v = 0 automatically)
            float4 q = strig[r][s];
            const float zr = Cr * q.z + Ci * q.w;
            const float zi = Ci * q.z - Cr * q.w;
            float vr = q.x * zr;                 // v = ct * C * conj(ep)
            float vi = q.x * zi;
            const float gwr = Cr * q.z - Ci * q.w;
            const float gwi = Ci * q.z + Cr * q.w;
            Cr = q.y * gwr;                      // C' = st * C * ep
            Ci = q.y * gwi;

#pragma unroll
            for (int j = 1; j < RANK; ++j) {
                // stage j: active for chains s < j, rows i <= 192+j
                // (i == 192+j is the sentinel: emits carry as this row's value)
                if (j > s && i <= BASE + j) {
                    q = strig[r][j];                 // uniform addr -> broadcast
                    const float2 a = carry[j][s];
                    const float ur = q.x * a.x - q.y * vr;   // u = ct*a - st*v
                    const float ui = q.x * a.y - q.y * vi;
                    const float pr = q.x * vr + q.y * a.x;   // w = ct*v + st*a
                    const float pi = q.x * vi + q.y * a.y;
                    vr = ur * q.z + ui * q.w;        // z = u * conj(ep)
                    vi = ui * q.z - ur * q.w;
                    carry[j][s] = make_float2(pr * q.z - pi * q.w,   // a' = w*ep
                                              pi * q.z + pr * q.w);
                }
            }

            // REAL PART, compact layout, scalar STG.32, guarded.
            const long long fo = ob + (long long)i * RANK + (RANK - 1 - s);
            if (fo < ocap) outf[fo] = vr;
        }
        __syncthreads();
    }
}

extern "C" void kernel_launch(void* const* d_in, const int* in_sizes, int n_in,
                              void* d_out, int out_size) {
    if (n_in < 1 || d_in == 0 || d_out == 0) return;

    // theta = the only large input (float32, confirmed by the passing R15).
    int ti = 0;
    for (int i = 1; i < n_in; ++i) {
        if (in_sizes[i] > in_sizes[ti]) ti = i;
    }
    const float* theta = (const float*)d_in[ti];
    const long long tcap = (long long)in_sizes[ti];   // theta float count

    long long ocap = (long long)out_size;
    if (ocap > NEED_FLOATS) ocap = NEED_FLOATS;
    if (ocap < 1) return;

    long long nb = tcap / THETA_STRIDE;
    const long long nb_out = ocap / OUT_BSTRIDE;
    if (nb_out < nb) nb = nb_out;
    if (nb < 1) nb = 1;
    if (nb > MAXB) nb = MAXB;

    stiefel_kernel<<<(int)nb, RANK>>>(theta, (float*)d_out, tcap, ocap);
}